// round 2
// baseline (speedup 1.0000x reference)
#include <cuda_runtime.h>
#include <math.h>

// ---------------- problem constants ----------------
#define D_MODEL 2048
#define NHEADS  16
#define HD      128
#define HD4     32            // float4 per head row
#define BATCH   2
#define SEQ     2048
#define MROWS   (BATCH*SEQ)   // 4096

// 7 scratch planes of [MROWS, D_MODEL] fp32: Qlin,Klin,Vlin,Qr,Kr,Vt,AttnO
__device__ float g_scratch[7ULL * MROWS * D_MODEL];

// ---------------- GEMM: C[M,N] = A[M,K] @ W[N,K]^T + bias[N] ----------------
#define GBM 128
#define GBN 64
#define GBK 16

__global__ __launch_bounds__(256) void gemm_bias_kernel(
    const float* __restrict__ A, const float* __restrict__ W,
    const float* __restrict__ bias, float* __restrict__ C,
    int M, int N, int K)
{
    __shared__ float As[GBK][GBM + 4];   // transposed tiles: [k][m]
    __shared__ float Bs[GBK][GBN + 4];   // [k][n]

    const int tid = threadIdx.x;         // 256 threads
    const int tx  = tid & 15;            // 16 col groups  * TN=4 -> 64
    const int ty  = tid >> 4;            // 16 row groups  * TM=8 -> 128
    const int rowBase = blockIdx.y * GBM;
    const int colBase = blockIdx.x * GBN;
    const int aC4 = tid & 3;             // float4 index along K (4*4=16)
    const int aR  = tid >> 2;            // 0..63

    float acc[8][4];
    #pragma unroll
    for (int i = 0; i < 8; i++)
        #pragma unroll
        for (int j = 0; j < 4; j++) acc[i][j] = 0.f;

    for (int k0 = 0; k0 < K; k0 += GBK) {
        // load A tile (128x16) as float4 along K, store transposed
        #pragma unroll
        for (int rr = 0; rr < 2; rr++) {
            int r = aR + rr * 64;
            float4 v = *(const float4*)(A + (size_t)(rowBase + r) * K + k0 + aC4 * 4);
            As[aC4*4+0][r] = v.x; As[aC4*4+1][r] = v.y;
            As[aC4*4+2][r] = v.z; As[aC4*4+3][r] = v.w;
        }
        // load W tile (64x16)
        {
            float4 v = *(const float4*)(W + (size_t)(colBase + aR) * K + k0 + aC4 * 4);
            Bs[aC4*4+0][aR] = v.x; Bs[aC4*4+1][aR] = v.y;
            Bs[aC4*4+2][aR] = v.z; Bs[aC4*4+3][aR] = v.w;
        }
        __syncthreads();

        #pragma unroll
        for (int kk = 0; kk < GBK; kk++) {
            float4 ra0 = *(const float4*)&As[kk][ty * 8];
            float4 ra1 = *(const float4*)&As[kk][ty * 8 + 4];
            float4 rb  = *(const float4*)&Bs[kk][tx * 4];
            float ra[8] = {ra0.x, ra0.y, ra0.z, ra0.w, ra1.x, ra1.y, ra1.z, ra1.w};
            float rbv[4] = {rb.x, rb.y, rb.z, rb.w};
            #pragma unroll
            for (int i = 0; i < 8; i++)
                #pragma unroll
                for (int j = 0; j < 4; j++)
                    acc[i][j] = fmaf(ra[i], rbv[j], acc[i][j]);
        }
        __syncthreads();
    }

    float4 bv = *(const float4*)(bias + colBase + tx * 4);
    #pragma unroll
    for (int i = 0; i < 8; i++) {
        size_t row = (size_t)(rowBase + ty * 8 + i);
        float4 o;
        o.x = acc[i][0] + bv.x; o.y = acc[i][1] + bv.y;
        o.z = acc[i][2] + bv.z; o.w = acc[i][3] + bv.w;
        *(float4*)(C + row * N + colBase + tx * 4) = o;
    }
}

// ---------------- RoPE (reference-exact: cos(emb)/sin(emb) of sin/cos!) + transpose ----------------
__global__ __launch_bounds__(256) void rope_transpose_kernel(
    const float* __restrict__ Qlin, const float* __restrict__ Klin,
    const float* __restrict__ Vlin,
    float* __restrict__ Qr, float* __restrict__ Kr, float* __restrict__ Vt)
{
    int idx = blockIdx.x * blockDim.x + threadIdx.x;   // [B,H,S,HD] flat
    int d = idx & (HD - 1);
    int s = (idx >> 7) & (SEQ - 1);
    int h = (idx >> 18) & (NHEADS - 1);
    int b = idx >> 22;

    size_t src = ((size_t)(b * SEQ + s)) * D_MODEL + h * HD + d;
    int j = d & 63;
    // inv_freq[j] = 10000^(-j/64) ; ln(10000)=9.210340371976184
    float invf = expf(-(float)j * (9.210340371976184f / 64.0f));
    float ang  = (float)s * invf;
    float e    = (d < 64) ? sinf(ang) : cosf(ang);     // emb
    float ce   = cosf(e);
    float se   = sinf(e);

    size_t srcP = (d < 64) ? src + 64 : src - 64;
    float sgn   = (d < 64) ? -1.0f : 1.0f;

    float q = Qlin[src], qp = Qlin[srcP];
    float k = Klin[src], kp = Klin[srcP];
    Qr[idx] = fmaf(q, ce, sgn * qp * se);
    Kr[idx] = fmaf(k, ce, sgn * kp * se);
    Vt[idx] = Vlin[src];
}

// ---------------- flash attention (fp32, online softmax) ----------------
#define TQ 32
#define TK 64
#define ATTN_THREADS 128

struct AttnSmem {
    float4 Qs[TQ][HD4 + 1];
    float4 Ks[TK][HD4 + 1];
    float4 Vs[TK][HD4 + 1];
    float  Sc[TQ][TK + 1];
    float  mrow[TQ];
    float  lrow[TQ];
    float  corr[TQ];
};

__global__ __launch_bounds__(ATTN_THREADS) void attn_kernel(
    const float* __restrict__ Qr, const float* __restrict__ Kr,
    const float* __restrict__ Vt, float* __restrict__ O)
{
    extern __shared__ char smemRaw[];
    AttnSmem& sm = *reinterpret_cast<AttnSmem*>(smemRaw);

    const int t    = threadIdx.x;
    const int lane = t & 31;            // query row owned by this thread
    const int w    = t >> 5;            // warp id: owns d-chunk [w*32,(w+1)*32)
    const int qBase = blockIdx.x * TQ;
    const int h = blockIdx.y;
    const int b = blockIdx.z;
    const size_t bh = (size_t)b * NHEADS + h;

    const float4* Qg = (const float4*)Qr + (bh * SEQ + qBase) * HD4;
    const float4* Kg = (const float4*)Kr + bh * SEQ * HD4;
    const float4* Vg = (const float4*)Vt + bh * SEQ * HD4;

    #pragma unroll
    for (int i = 0; i < (TQ * HD4) / ATTN_THREADS; i++) {
        int idx = t + i * ATTN_THREADS;
        sm.Qs[idx >> 5][idx & 31] = Qg[idx];
    }
    if (t < TQ) { sm.mrow[t] = -INFINITY; sm.lrow[t] = 0.f; }

    float4 acc[8];
    #pragma unroll
    for (int u = 0; u < 8; u++) acc[u] = make_float4(0.f, 0.f, 0.f, 0.f);
    __syncthreads();

    const float SCALE = 0.08838834764831845f;   // 1/sqrt(128)

    for (int kt = 0; kt < SEQ / TK; kt++) {
        // load K,V tiles (coalesced float4)
        #pragma unroll
        for (int i = 0; i < (TK * HD4) / ATTN_THREADS; i++) {
            int idx = t + i * ATTN_THREADS;
            sm.Ks[idx >> 5][idx & 31] = Kg[kt * TK * HD4 + idx];
            sm.Vs[idx >> 5][idx & 31] = Vg[kt * TK * HD4 + idx];
        }
        __syncthreads();

        // scores: thread (lane,w) computes Sc[lane][w*16 .. w*16+15]
        float sAcc[16];
        #pragma unroll
        for (int jj = 0; jj < 16; jj++) sAcc[jj] = 0.f;
        #pragma unroll
        for (int c = 0; c < 4; c++) {
            float4 rq[8];
            #pragma unroll
            for (int u = 0; u < 8; u++) rq[u] = sm.Qs[lane][c * 8 + u];
            #pragma unroll
            for (int jj = 0; jj < 16; jj++) {
                int kj = w * 16 + jj;
                #pragma unroll
                for (int u = 0; u < 8; u++) {
                    float4 rk = sm.Ks[kj][c * 8 + u];
                    sAcc[jj] = fmaf(rq[u].x, rk.x, sAcc[jj]);
                    sAcc[jj] = fmaf(rq[u].y, rk.y, sAcc[jj]);
                    sAcc[jj] = fmaf(rq[u].z, rk.z, sAcc[jj]);
                    sAcc[jj] = fmaf(rq[u].w, rk.w, sAcc[jj]);
                }
            }
        }
        #pragma unroll
        for (int jj = 0; jj < 16; jj++)
            sm.Sc[lane][w * 16 + jj] = sAcc[jj] * SCALE;
        __syncthreads();

        // online softmax, one thread per query row
        if (t < TQ) {
            float mOld = sm.mrow[t];
            float mNew = mOld;
            for (int j2 = 0; j2 < TK; j2++) mNew = fmaxf(mNew, sm.Sc[t][j2]);
            float c = __expf(mOld - mNew);
            float lsum = 0.f;
            for (int j2 = 0; j2 < TK; j2++) {
                float p = __expf(sm.Sc[t][j2] - mNew);
                sm.Sc[t][j2] = p;
                lsum += p;
            }
            sm.mrow[t] = mNew;
            sm.lrow[t] = sm.lrow[t] * c + lsum;
            sm.corr[t] = c;
        }
        __syncthreads();

        // O += P @ V  (register accumulators; Vs reads are warp-broadcast)
        {
            float c = sm.corr[lane];
            #pragma unroll
            for (int u = 0; u < 8; u++) {
                acc[u].x *= c; acc[u].y *= c; acc[u].z *= c; acc[u].w *= c;
            }
            for (int kj = 0; kj < TK; kj++) {
                float p = sm.Sc[lane][kj];
                #pragma unroll
                for (int u = 0; u < 8; u++) {
                    float4 v = sm.Vs[kj][w * 8 + u];
                    acc[u].x = fmaf(p, v.x, acc[u].x);
                    acc[u].y = fmaf(p, v.y, acc[u].y);
                    acc[u].z = fmaf(p, v.z, acc[u].z);
                    acc[u].w = fmaf(p, v.w, acc[u].w);
                }
            }
        }
        __syncthreads();
    }

    // normalize, stage in smem, write coalesced to [B,S,H*HD] layout
    float invl = 1.0f / sm.lrow[lane];
    #pragma unroll
    for (int u = 0; u < 8; u++) {
        float4 o = acc[u];
        o.x *= invl; o.y *= invl; o.z *= invl; o.w *= invl;
        sm.Qs[lane][w * 8 + u] = o;
    }
    __syncthreads();

    float4* Og = (float4*)O + ((size_t)(b * SEQ + qBase)) * (D_MODEL / 4) + h * HD4;
    #pragma unroll
    for (int i = 0; i < (TQ * HD4) / ATTN_THREADS; i++) {
        int idx = t + i * ATTN_THREADS;
        Og[(idx >> 5) * (D_MODEL / 4) + (idx & 31)] = sm.Qs[idx >> 5][idx & 31];
    }
}

// ---------------- launch ----------------
extern "C" void kernel_launch(void* const* d_in, const int* in_sizes, int n_in,
                              void* d_out, int out_size)
{
    const float* x  = (const float*)d_in[0];
    const float* Wq = (const float*)d_in[1];
    const float* bq = (const float*)d_in[2];
    const float* Wk = (const float*)d_in[3];
    const float* bk = (const float*)d_in[4];
    const float* Wv = (const float*)d_in[5];
    const float* bv = (const float*)d_in[6];
    const float* Wo = (const float*)d_in[7];
    const float* bo = (const float*)d_in[8];
    float* out = (float*)d_out;

    float* scratch = nullptr;
    cudaGetSymbolAddress((void**)&scratch, g_scratch);
    const size_t NMe = (size_t)MROWS * D_MODEL;
    float* Qlin = scratch + 0 * NMe;
    float* Klin = scratch + 1 * NMe;
    float* Vlin = scratch + 2 * NMe;
    float* Qr   = scratch + 3 * NMe;
    float* Kr   = scratch + 4 * NMe;
    float* Vt   = scratch + 5 * NMe;
    float* AO   = scratch + 6 * NMe;

    dim3 ggrid(D_MODEL / GBN, MROWS / GBM);
    gemm_bias_kernel<<<ggrid, 256>>>(x, Wq, bq, Qlin, MROWS, D_MODEL, D_MODEL);
    gemm_bias_kernel<<<ggrid, 256>>>(x, Wk, bk, Klin, MROWS, D_MODEL, D_MODEL);
    gemm_bias_kernel<<<ggrid, 256>>>(x, Wv, bv, Vlin, MROWS, D_MODEL, D_MODEL);

    int total = BATCH * NHEADS * SEQ * HD;
    rope_transpose_kernel<<<total / 256, 256>>>(Qlin, Klin, Vlin, Qr, Kr, Vt);

    cudaFuncSetAttribute(attn_kernel, cudaFuncAttributeMaxDynamicSharedMemorySize,
                         (int)sizeof(AttnSmem));
    attn_kernel<<<dim3(SEQ / TQ, NHEADS, BATCH), ATTN_THREADS, sizeof(AttnSmem)>>>(Qr, Kr, Vt, AO);

    gemm_bias_kernel<<<ggrid, 256>>>(AO, Wo, bo, out, MROWS, D_MODEL, D_MODEL);
}

// round 6
// speedup vs baseline: 2.1787x; 2.1787x over previous
#include <cuda_runtime.h>
#include <cuda_bf16.h>
#include <math.h>
#include <stdint.h>

// ---------------- problem constants ----------------
#define D_MODEL 2048
#define NHEADS  16
#define HD      128
#define HD4     32
#define BATCH   2
#define SEQ     2048
#define MROWS   (BATCH*SEQ)   // 4096
#define KTOT    (3*D_MODEL)   // 6144 (3-term bf16 split along K)

// fp32 scratch: Qlin,Klin,Vlin,Qr,Kr,Vt,AO
__device__ float g_scratch[7ULL * MROWS * D_MODEL];
// bf16 scratch: Xhat[4096,6144], AOhat[4096,6144], 4x What[2048,6144]
__device__ __nv_bfloat16 g_bf16[2ULL * MROWS * KTOT + 4ULL * D_MODEL * KTOT];

// ---------------- PTX helpers (portable: sm_80-era only) ----------------
__device__ __forceinline__ uint32_t smem_u32(const void* p) {
    uint32_t r;
    asm("{ .reg .u64 t; cvta.to.shared.u64 t, %1; cvt.u32.u64 %0, t; }"
        : "=r"(r) : "l"(p));
    return r;
}

__device__ __forceinline__ void cp16(uint32_t dst, const void* src) {
    asm volatile("cp.async.cg.shared.global [%0], [%1], 16;"
                 :: "r"(dst), "l"(src));
}

__device__ __forceinline__ void ldsm_x4(uint32_t& r0, uint32_t& r1,
                                        uint32_t& r2, uint32_t& r3, uint32_t addr) {
    asm volatile("ldmatrix.sync.aligned.m8n8.x4.shared.b16 {%0,%1,%2,%3}, [%4];"
                 : "=r"(r0), "=r"(r1), "=r"(r2), "=r"(r3) : "r"(addr));
}

__device__ __forceinline__ void mma_bf16(float* d, const uint32_t* a, const uint32_t* b) {
    asm volatile(
        "mma.sync.aligned.m16n8k16.row.col.f32.bf16.bf16.f32 "
        "{%0,%1,%2,%3}, {%4,%5,%6,%7}, {%8,%9}, {%0,%1,%2,%3};"
        : "+f"(d[0]), "+f"(d[1]), "+f"(d[2]), "+f"(d[3])
        : "r"(a[0]), "r"(a[1]), "r"(a[2]), "r"(a[3]), "r"(b[0]), "r"(b[1]));
}

// ---------------- split fp32 -> 3-term bf16 ----------------
// A-side (isW=0): [hi | lo | hi]    W-side (isW=1): [hi | hi | lo]
__global__ __launch_bounds__(256) void split_kernel(
    const float* __restrict__ in, __nv_bfloat16* __restrict__ out, int isW)
{
    int idx = blockIdx.x * 256 + threadIdx.x;
    int r = idx >> 11;
    int k = idx & 2047;
    float v = in[idx];
    __nv_bfloat16 hi = __float2bfloat16(v);
    __nv_bfloat16 lo = __float2bfloat16(v - __bfloat162float(hi));
    __nv_bfloat16* o = out + (size_t)r * KTOT;
    if (isW) { o[k] = hi; o[D_MODEL + k] = hi; o[2 * D_MODEL + k] = lo; }
    else     { o[k] = hi; o[D_MODEL + k] = lo; o[2 * D_MODEL + k] = hi; }
}

// ---------------- mma.sync bf16 GEMM: C[M,N] = A @ B^T + bias ----------------
// A [M,KTOT] bf16 row-major, B [N,KTOT] bf16 row-major, C fp32.
#define BM 128
#define BN 128
#define BK 32
#define NSTAGE 3
#define NT (KTOT / BK)               // 192
#define ROWB 80                      // 64B data + 16B pad (conflict-free ldmatrix)
#define A_BYTES (BM * ROWB)          // 10240
#define STAGE_BYTES (2 * BM * ROWB)  // 20480 (A + B)
#define GEMM_SMEM (NSTAGE * STAGE_BYTES)  // 61440

__global__ __launch_bounds__(256) void gemm_mma_kernel(
    const __nv_bfloat16* __restrict__ A, const __nv_bfloat16* __restrict__ B,
    const float* __restrict__ bias, float* __restrict__ C, int M, int N)
{
    extern __shared__ __align__(128) char smraw[];
    const uint32_t smb = smem_u32(smraw);
    const int tid  = threadIdx.x;
    const int lane = tid & 31;
    const int wid  = tid >> 5;
    const int wm   = (wid >> 2) * 64;   // warp m offset (2 warps along M)
    const int wn   = (wid & 3) * 32;    // warp n offset (4 warps along N)
    const int rowBase = blockIdx.y * BM;
    const int colBase = blockIdx.x * BN;

    const char* Ag = (const char*)A + (size_t)rowBase * (KTOT * 2);
    const char* Bg = (const char*)B + (size_t)colBase * (KTOT * 2);

    float acc[4][4][4];
    #pragma unroll
    for (int mi = 0; mi < 4; mi++)
        #pragma unroll
        for (int ni = 0; ni < 4; ni++)
            #pragma unroll
            for (int u = 0; u < 4; u++) acc[mi][ni][u] = 0.f;

    // loader mapping: 512 16B-chunks per operand tile; 256 threads x 2 chunks
    const int lr0 = tid >> 2;           // row for chunk 0 (0..63)
    const int lc  = (tid & 3) * 16;     // byte col within 64B row

    auto load_stage = [&](int kt) {
        if (kt < NT) {
            uint32_t base = smb + (kt % NSTAGE) * STAGE_BYTES;
            const size_t gk = (size_t)kt * 64;
            #pragma unroll
            for (int i = 0; i < 2; i++) {
                int r = lr0 + i * 64;
                cp16(base + r * ROWB + lc, Ag + (size_t)r * (KTOT * 2) + gk + lc);
            }
            #pragma unroll
            for (int i = 0; i < 2; i++) {
                int r = lr0 + i * 64;
                cp16(base + A_BYTES + r * ROWB + lc,
                     Bg + (size_t)r * (KTOT * 2) + gk + lc);
            }
        }
        asm volatile("cp.async.commit_group;" ::: "memory");
    };

    load_stage(0);
    load_stage(1);

    // ldmatrix lane addressing
    const int a_row  = lane & 15;            // rows 0-15 of 16x16 A frag
    const int a_half = (lane >> 4) * 16;     // k half (bytes)
    const int b_row  = ((lane >> 4) << 3) + (lane & 7);  // n row within n16
    const int b_half = ((lane >> 3) & 1) * 16;           // k half (bytes)

    for (int kt = 0; kt < NT; kt++) {
        asm volatile("cp.async.wait_group %0;" :: "n"(NSTAGE - 2) : "memory");
        __syncthreads();
        load_stage(kt + NSTAGE - 1);

        uint32_t aBase = smb + (kt % NSTAGE) * STAGE_BYTES;
        uint32_t bBase = aBase + A_BYTES;

        #pragma unroll
        for (int j = 0; j < 2; j++) {        // two k16 steps per BK=32
            uint32_t af[4][4];
            #pragma unroll
            for (int mi = 0; mi < 4; mi++)
                ldsm_x4(af[mi][0], af[mi][1], af[mi][2], af[mi][3],
                        aBase + (wm + mi * 16 + a_row) * ROWB + j * 32 + a_half);
            uint32_t bf[2][4];
            #pragma unroll
            for (int nb = 0; nb < 2; nb++)   // two n16 blocks -> 4 n8 frags
                ldsm_x4(bf[nb][0], bf[nb][1], bf[nb][2], bf[nb][3],
                        bBase + (wn + nb * 16 + b_row) * ROWB + j * 32 + b_half);
            #pragma unroll
            for (int mi = 0; mi < 4; mi++)
                #pragma unroll
                for (int ni = 0; ni < 4; ni++)
                    mma_bf16(acc[mi][ni], af[mi], &bf[ni >> 1][(ni & 1) * 2]);
        }
        __syncthreads();
    }

    // epilogue: direct fp32 stores + bias
    #pragma unroll
    for (int mi = 0; mi < 4; mi++) {
        int r0 = rowBase + wm + mi * 16 + (lane >> 2);
        #pragma unroll
        for (int ni = 0; ni < 4; ni++) {
            int cn = colBase + wn + ni * 8 + (lane & 3) * 2;
            float2 bv = *(const float2*)(bias + cn);
            float2 o0, o1;
            o0.x = acc[mi][ni][0] + bv.x; o0.y = acc[mi][ni][1] + bv.y;
            o1.x = acc[mi][ni][2] + bv.x; o1.y = acc[mi][ni][3] + bv.y;
            *(float2*)(C + (size_t)r0 * N + cn) = o0;
            *(float2*)(C + (size_t)(r0 + 8) * N + cn) = o1;
        }
    }
}

// ---------------- RoPE (reference-exact) + transpose ----------------
__global__ __launch_bounds__(256) void rope_transpose_kernel(
    const float* __restrict__ Qlin, const float* __restrict__ Klin,
    const float* __restrict__ Vlin,
    float* __restrict__ Qr, float* __restrict__ Kr, float* __restrict__ Vt)
{
    int idx = blockIdx.x * blockDim.x + threadIdx.x;   // [B,H,S,HD] flat
    int d = idx & (HD - 1);
    int s = (idx >> 7) & (SEQ - 1);
    int h = (idx >> 18) & (NHEADS - 1);
    int b = idx >> 22;

    size_t src = ((size_t)(b * SEQ + s)) * D_MODEL + h * HD + d;
    int j = d & 63;
    float invf = expf(-(float)j * (9.210340371976184f / 64.0f));
    float ang  = (float)s * invf;
    float e    = (d < 64) ? sinf(ang) : cosf(ang);     // emb
    float ce   = cosf(e);
    float se   = sinf(e);

    size_t srcP = (d < 64) ? src + 64 : src - 64;
    float sgn   = (d < 64) ? -1.0f : 1.0f;

    float q = Qlin[src], qp = Qlin[srcP];
    float k = Klin[src], kp = Klin[srcP];
    Qr[idx] = fmaf(q, ce, sgn * qp * se);
    Kr[idx] = fmaf(k, ce, sgn * kp * se);
    Vt[idx] = Vlin[src];
}

// ---------------- flash attention (fp32, online softmax) ----------------
#define TQ 32
#define TK 64
#define ATTN_THREADS 128

struct AttnSmem {
    float4 Qs[TQ][HD4 + 1];
    float4 Ks[TK][HD4 + 1];
    float4 Vs[TK][HD4 + 1];
    float  Sc[TQ][TK + 1];
    float  mrow[TQ];
    float  lrow[TQ];
    float  corr[TQ];
};

__global__ __launch_bounds__(ATTN_THREADS) void attn_kernel(
    const float* __restrict__ Qr, const float* __restrict__ Kr,
    const float* __restrict__ Vt, float* __restrict__ O)
{
    extern __shared__ char smemRaw[];
    AttnSmem& sm = *reinterpret_cast<AttnSmem*>(smemRaw);

    const int t    = threadIdx.x;
    const int lane = t & 31;
    const int w    = t >> 5;
    const int qBase = blockIdx.x * TQ;
    const int h = blockIdx.y;
    const int b = blockIdx.z;
    const size_t bh = (size_t)b * NHEADS + h;

    const float4* Qg = (const float4*)Qr + (bh * SEQ + qBase) * HD4;
    const float4* Kg = (const float4*)Kr + bh * SEQ * HD4;
    const float4* Vg = (const float4*)Vt + bh * SEQ * HD4;

    #pragma unroll
    for (int i = 0; i < (TQ * HD4) / ATTN_THREADS; i++) {
        int idx = t + i * ATTN_THREADS;
        sm.Qs[idx >> 5][idx & 31] = Qg[idx];
    }
    if (t < TQ) { sm.mrow[t] = -INFINITY; sm.lrow[t] = 0.f; }

    float4 acc[8];
    #pragma unroll
    for (int u = 0; u < 8; u++) acc[u] = make_float4(0.f, 0.f, 0.f, 0.f);
    __syncthreads();

    const float SCALE = 0.08838834764831845f;

    for (int kt = 0; kt < SEQ / TK; kt++) {
        #pragma unroll
        for (int i = 0; i < (TK * HD4) / ATTN_THREADS; i++) {
            int idx = t + i * ATTN_THREADS;
            sm.Ks[idx >> 5][idx & 31] = Kg[kt * TK * HD4 + idx];
            sm.Vs[idx >> 5][idx & 31] = Vg[kt * TK * HD4 + idx];
        }
        __syncthreads();

        float sAcc[16];
        #pragma unroll
        for (int jj = 0; jj < 16; jj++) sAcc[jj] = 0.f;
        #pragma unroll
        for (int c = 0; c < 4; c++) {
            float4 rq[8];
            #pragma unroll
            for (int u = 0; u < 8; u++) rq[u] = sm.Qs[lane][c * 8 + u];
            #pragma unroll
            for (int jj = 0; jj < 16; jj++) {
                int kj = w * 16 + jj;
                #pragma unroll
                for (int u = 0; u < 8; u++) {
                    float4 rk = sm.Ks[kj][c * 8 + u];
                    sAcc[jj] = fmaf(rq[u].x, rk.x, sAcc[jj]);
                    sAcc[jj] = fmaf(rq[u].y, rk.y, sAcc[jj]);
                    sAcc[jj] = fmaf(rq[u].z, rk.z, sAcc[jj]);
                    sAcc[jj] = fmaf(rq[u].w, rk.w, sAcc[jj]);
                }
            }
        }
        #pragma unroll
        for (int jj = 0; jj < 16; jj++)
            sm.Sc[lane][w * 16 + jj] = sAcc[jj] * SCALE;
        __syncthreads();

        if (t < TQ) {
            float mOld = sm.mrow[t];
            float mNew = mOld;
            for (int j2 = 0; j2 < TK; j2++) mNew = fmaxf(mNew, sm.Sc[t][j2]);
            float c = __expf(mOld - mNew);
            float lsum = 0.f;
            for (int j2 = 0; j2 < TK; j2++) {
                float p = __expf(sm.Sc[t][j2] - mNew);
                sm.Sc[t][j2] = p;
                lsum += p;
            }
            sm.mrow[t] = mNew;
            sm.lrow[t] = sm.lrow[t] * c + lsum;
            sm.corr[t] = c;
        }
        __syncthreads();

        {
            float c = sm.corr[lane];
            #pragma unroll
            for (int u = 0; u < 8; u++) {
                acc[u].x *= c; acc[u].y *= c; acc[u].z *= c; acc[u].w *= c;
            }
            for (int kj = 0; kj < TK; kj++) {
                float p = sm.Sc[lane][kj];
                #pragma unroll
                for (int u = 0; u < 8; u++) {
                    float4 v = sm.Vs[kj][w * 8 + u];
                    acc[u].x = fmaf(p, v.x, acc[u].x);
                    acc[u].y = fmaf(p, v.y, acc[u].y);
                    acc[u].z = fmaf(p, v.z, acc[u].z);
                    acc[u].w = fmaf(p, v.w, acc[u].w);
                }
            }
        }
        __syncthreads();
    }

    float invl = 1.0f / sm.lrow[lane];
    #pragma unroll
    for (int u = 0; u < 8; u++) {
        float4 o = acc[u];
        o.x *= invl; o.y *= invl; o.z *= invl; o.w *= invl;
        sm.Qs[lane][w * 8 + u] = o;
    }
    __syncthreads();

    float4* Og = (float4*)O + ((size_t)(b * SEQ + qBase)) * (D_MODEL / 4) + h * HD4;
    #pragma unroll
    for (int i = 0; i < (TQ * HD4) / ATTN_THREADS; i++) {
        int idx = t + i * ATTN_THREADS;
        Og[(idx >> 5) * (D_MODEL / 4) + (idx & 31)] = sm.Qs[idx >> 5][idx & 31];
    }
}

// ---------------- launch ----------------
extern "C" void kernel_launch(void* const* d_in, const int* in_sizes, int n_in,
                              void* d_out, int out_size)
{
    const float* x  = (const float*)d_in[0];
    const float* Wq = (const float*)d_in[1];
    const float* bq = (const float*)d_in[2];
    const float* Wk = (const float*)d_in[3];
    const float* bk = (const float*)d_in[4];
    const float* Wv = (const float*)d_in[5];
    const float* bv = (const float*)d_in[6];
    const float* Wo = (const float*)d_in[7];
    const float* bo = (const float*)d_in[8];
    float* out = (float*)d_out;

    float* scratch = nullptr;
    cudaGetSymbolAddress((void**)&scratch, g_scratch);
    const size_t NMe = (size_t)MROWS * D_MODEL;
    float* Qlin = scratch + 0 * NMe;
    float* Klin = scratch + 1 * NMe;
    float* Vlin = scratch + 2 * NMe;
    float* Qr   = scratch + 3 * NMe;
    float* Kr   = scratch + 4 * NMe;
    float* Vt   = scratch + 5 * NMe;
    float* AO   = scratch + 6 * NMe;

    __nv_bfloat16* bfp = nullptr;
    cudaGetSymbolAddress((void**)&bfp, g_bf16);
    const size_t XH = (size_t)MROWS * KTOT;
    const size_t WH = (size_t)D_MODEL * KTOT;
    __nv_bfloat16* Xhat  = bfp;
    __nv_bfloat16* AOhat = bfp + XH;
    __nv_bfloat16* WqH   = bfp + 2 * XH;
    __nv_bfloat16* WkH   = WqH + WH;
    __nv_bfloat16* WvH   = WkH + WH;
    __nv_bfloat16* WoH   = WvH + WH;

    cudaFuncSetAttribute(gemm_mma_kernel, cudaFuncAttributeMaxDynamicSharedMemorySize,
                         GEMM_SMEM);
    cudaFuncSetAttribute(attn_kernel, cudaFuncAttributeMaxDynamicSharedMemorySize,
                         (int)sizeof(AttnSmem));

    // split operands to 3-term bf16
    split_kernel<<<(MROWS * D_MODEL) / 256, 256>>>(x,  Xhat, 0);
    split_kernel<<<(D_MODEL * D_MODEL) / 256, 256>>>(Wq, WqH, 1);
    split_kernel<<<(D_MODEL * D_MODEL) / 256, 256>>>(Wk, WkH, 1);
    split_kernel<<<(D_MODEL * D_MODEL) / 256, 256>>>(Wv, WvH, 1);
    split_kernel<<<(D_MODEL * D_MODEL) / 256, 256>>>(Wo, WoH, 1);

    dim3 ggrid(D_MODEL / BN, MROWS / BM);   // (16, 32)
    gemm_mma_kernel<<<ggrid, 256, GEMM_SMEM>>>(Xhat, WqH, bq, Qlin, MROWS, D_MODEL);
    gemm_mma_kernel<<<ggrid, 256, GEMM_SMEM>>>(Xhat, WkH, bk, Klin, MROWS, D_MODEL);
    gemm_mma_kernel<<<ggrid, 256, GEMM_SMEM>>>(Xhat, WvH, bv, Vlin, MROWS, D_MODEL);

    int total = BATCH * NHEADS * SEQ * HD;
    rope_transpose_kernel<<<total / 256, 256>>>(Qlin, Klin, Vlin, Qr, Kr, Vt);

    attn_kernel<<<dim3(SEQ / TQ, NHEADS, BATCH), ATTN_THREADS, sizeof(AttnSmem)>>>(Qr, Kr, Vt, AO);

    split_kernel<<<(MROWS * D_MODEL) / 256, 256>>>(AO, AOhat, 0);
    gemm_mma_kernel<<<ggrid, 256, GEMM_SMEM>>>(AOhat, WoH, bo, out, MROWS, D_MODEL);
}

// round 10
// speedup vs baseline: 4.0950x; 1.8796x over previous
#include <cuda_runtime.h>
#include <cuda_bf16.h>
#include <math.h>
#include <stdint.h>

// ---------------- problem constants ----------------
#define D_MODEL 2048
#define NHEADS  16
#define HD      128
#define BATCH   2
#define SEQ     2048
#define MROWS   (BATCH*SEQ)   // 4096
#define KTOT    (3*D_MODEL)   // 6144 (3-term bf16 split along K)
#define BHS     (BATCH*NHEADS*SEQ)   // 65536 rows of HD

// fp32 scratch: Qlin,Klin,Vlin,AO (+spare)
__device__ float g_scratch[5ULL * MROWS * D_MODEL];
// bf16 scratch for GEMMs: Xhat, AOhat, 4x What
__device__ __nv_bfloat16 g_bf16[2ULL * MROWS * KTOT + 4ULL * D_MODEL * KTOT];
// bf16 scratch for attention: Qhi,Qlo,Khi,Klo,Vhi,Vlo each [B,H,S,HD]
__device__ __nv_bfloat16 g_attn[6ULL * BHS * HD];

// ---------------- PTX helpers (portable: sm_75/80-era only) ----------------
__device__ __forceinline__ uint32_t smem_u32(const void* p) {
    uint32_t r;
    asm("{ .reg .u64 t; cvta.to.shared.u64 t, %1; cvt.u32.u64 %0, t; }"
        : "=r"(r) : "l"(p));
    return r;
}

__device__ __forceinline__ void cp16(uint32_t dst, const void* src) {
    asm volatile("cp.async.cg.shared.global [%0], [%1], 16;"
                 :: "r"(dst), "l"(src));
}

__device__ __forceinline__ void ldsm_x4(uint32_t* r, uint32_t addr) {
    asm volatile("ldmatrix.sync.aligned.m8n8.x4.shared.b16 {%0,%1,%2,%3}, [%4];"
                 : "=r"(r[0]), "=r"(r[1]), "=r"(r[2]), "=r"(r[3]) : "r"(addr));
}

__device__ __forceinline__ void ldsm_x4_t(uint32_t* r, uint32_t addr) {
    asm volatile("ldmatrix.sync.aligned.m8n8.x4.trans.shared.b16 {%0,%1,%2,%3}, [%4];"
                 : "=r"(r[0]), "=r"(r[1]), "=r"(r[2]), "=r"(r[3]) : "r"(addr));
}

__device__ __forceinline__ void mma_bf16(float* d, const uint32_t* a, const uint32_t* b) {
    asm volatile(
        "mma.sync.aligned.m16n8k16.row.col.f32.bf16.bf16.f32 "
        "{%0,%1,%2,%3}, {%4,%5,%6,%7}, {%8,%9}, {%0,%1,%2,%3};"
        : "+f"(d[0]), "+f"(d[1]), "+f"(d[2]), "+f"(d[3])
        : "r"(a[0]), "r"(a[1]), "r"(a[2]), "r"(a[3]), "r"(b[0]), "r"(b[1]));
}

__device__ __forceinline__ void pack_hilo(float a, float b, uint32_t& hi, uint32_t& lo) {
    __nv_bfloat162 th, tl;
    th.x = __float2bfloat16(a);
    th.y = __float2bfloat16(b);
    tl.x = __float2bfloat16(a - __bfloat162float(th.x));
    tl.y = __float2bfloat16(b - __bfloat162float(th.y));
    hi = *(uint32_t*)&th;
    lo = *(uint32_t*)&tl;
}

// ---------------- split fp32 -> 3-term bf16 ----------------
// A-side (isW=0): [hi | lo | hi]    W-side (isW=1): [hi | hi | lo]
__global__ __launch_bounds__(256) void split_kernel(
    const float* __restrict__ in, __nv_bfloat16* __restrict__ out, int isW)
{
    int idx = blockIdx.x * 256 + threadIdx.x;
    int r = idx >> 11;
    int k = idx & 2047;
    float v = in[idx];
    __nv_bfloat16 hi = __float2bfloat16(v);
    __nv_bfloat16 lo = __float2bfloat16(v - __bfloat162float(hi));
    __nv_bfloat16* o = out + (size_t)r * KTOT;
    if (isW) { o[k] = hi; o[D_MODEL + k] = hi; o[2 * D_MODEL + k] = lo; }
    else     { o[k] = hi; o[D_MODEL + k] = lo; o[2 * D_MODEL + k] = hi; }
}

// ---------------- mma.sync bf16 GEMM: C[M,N] = A @ B^T + bias ----------------
#define BM 128
#define BN 128
#define BK 32
#define NSTAGE 3
#define NT (KTOT / BK)               // 192
#define ROWB 80
#define A_BYTES (BM * ROWB)          // 10240
#define STAGE_BYTES (2 * BM * ROWB)  // 20480
#define GEMM_SMEM (NSTAGE * STAGE_BYTES)  // 61440

__global__ __launch_bounds__(256) void gemm_mma_kernel(
    const __nv_bfloat16* __restrict__ A, const __nv_bfloat16* __restrict__ B,
    const float* __restrict__ bias, float* __restrict__ C, int M, int N)
{
    extern __shared__ __align__(128) char smraw[];
    const uint32_t smb = smem_u32(smraw);
    const int tid  = threadIdx.x;
    const int lane = tid & 31;
    const int wid  = tid >> 5;
    const int wm   = (wid >> 2) * 64;
    const int wn   = (wid & 3) * 32;
    const int rowBase = blockIdx.y * BM;
    const int colBase = blockIdx.x * BN;

    const char* Ag = (const char*)A + (size_t)rowBase * (KTOT * 2);
    const char* Bg = (const char*)B + (size_t)colBase * (KTOT * 2);

    float acc[4][4][4];
    #pragma unroll
    for (int mi = 0; mi < 4; mi++)
        #pragma unroll
        for (int ni = 0; ni < 4; ni++)
            #pragma unroll
            for (int u = 0; u < 4; u++) acc[mi][ni][u] = 0.f;

    const int lr0 = tid >> 2;
    const int lc  = (tid & 3) * 16;

    auto load_stage = [&](int kt) {
        if (kt < NT) {
            uint32_t base = smb + (kt % NSTAGE) * STAGE_BYTES;
            const size_t gk = (size_t)kt * 64;
            #pragma unroll
            for (int i = 0; i < 2; i++) {
                int r = lr0 + i * 64;
                cp16(base + r * ROWB + lc, Ag + (size_t)r * (KTOT * 2) + gk + lc);
            }
            #pragma unroll
            for (int i = 0; i < 2; i++) {
                int r = lr0 + i * 64;
                cp16(base + A_BYTES + r * ROWB + lc,
                     Bg + (size_t)r * (KTOT * 2) + gk + lc);
            }
        }
        asm volatile("cp.async.commit_group;" ::: "memory");
    };

    load_stage(0);
    load_stage(1);

    const int a_row  = lane & 15;
    const int a_half = (lane >> 4) * 16;
    const int b_row  = ((lane >> 4) << 3) + (lane & 7);
    const int b_half = ((lane >> 3) & 1) * 16;

    for (int kt = 0; kt < NT; kt++) {
        asm volatile("cp.async.wait_group %0;" :: "n"(NSTAGE - 2) : "memory");
        __syncthreads();
        load_stage(kt + NSTAGE - 1);

        uint32_t aBase = smb + (kt % NSTAGE) * STAGE_BYTES;
        uint32_t bBase = aBase + A_BYTES;

        #pragma unroll
        for (int j = 0; j < 2; j++) {
            uint32_t af[4][4];
            #pragma unroll
            for (int mi = 0; mi < 4; mi++)
                ldsm_x4(af[mi],
                        aBase + (wm + mi * 16 + a_row) * ROWB + j * 32 + a_half);
            uint32_t bf[2][4];
            #pragma unroll
            for (int nb = 0; nb < 2; nb++)
                ldsm_x4(bf[nb],
                        bBase + (wn + nb * 16 + b_row) * ROWB + j * 32 + b_half);
            #pragma unroll
            for (int mi = 0; mi < 4; mi++)
                #pragma unroll
                for (int ni = 0; ni < 4; ni++)
                    mma_bf16(acc[mi][ni], af[mi], &bf[ni >> 1][(ni & 1) * 2]);
        }
        __syncthreads();
    }

    #pragma unroll
    for (int mi = 0; mi < 4; mi++) {
        int r0 = rowBase + wm + mi * 16 + (lane >> 2);
        #pragma unroll
        for (int ni = 0; ni < 4; ni++) {
            int cn = colBase + wn + ni * 8 + (lane & 3) * 2;
            float2 bv = *(const float2*)(bias + cn);
            float2 o0, o1;
            o0.x = acc[mi][ni][0] + bv.x; o0.y = acc[mi][ni][1] + bv.y;
            o1.x = acc[mi][ni][2] + bv.x; o1.y = acc[mi][ni][3] + bv.y;
            *(float2*)(C + (size_t)r0 * N + cn) = o0;
            *(float2*)(C + (size_t)(r0 + 8) * N + cn) = o1;
        }
    }
}

// ---------------- RoPE (reference-exact) -> bf16 hi/lo Q,K,V [B,H,S,HD] ----------------
__global__ __launch_bounds__(256) void rope_split_kernel(
    const float* __restrict__ Qlin, const float* __restrict__ Klin,
    const float* __restrict__ Vlin,
    __nv_bfloat16* __restrict__ Qhi, __nv_bfloat16* __restrict__ Qlo,
    __nv_bfloat16* __restrict__ Khi, __nv_bfloat16* __restrict__ Klo,
    __nv_bfloat16* __restrict__ Vhi, __nv_bfloat16* __restrict__ Vlo)
{
    int idx = blockIdx.x * blockDim.x + threadIdx.x;   // [B,H,S,HD] flat
    int d = idx & (HD - 1);
    int s = (idx >> 7) & (SEQ - 1);
    int h = (idx >> 18) & (NHEADS - 1);
    int b = idx >> 22;

    size_t src = ((size_t)(b * SEQ + s)) * D_MODEL + h * HD + d;
    int j = d & 63;
    float invf = expf(-(float)j * (9.210340371976184f / 64.0f));
    float ang  = (float)s * invf;
    float e    = (d < 64) ? sinf(ang) : cosf(ang);     // emb (reference quirk)
    float ce   = cosf(e);
    float se   = sinf(e);

    size_t srcP = (d < 64) ? src + 64 : src - 64;
    float sgn   = (d < 64) ? -1.0f : 1.0f;

    float q = Qlin[src], qp = Qlin[srcP];
    float k = Klin[src], kp = Klin[srcP];
    float qr = fmaf(q, ce, sgn * qp * se);
    float kr = fmaf(k, ce, sgn * kp * se);
    float v  = Vlin[src];

    __nv_bfloat16 qh = __float2bfloat16(qr);
    __nv_bfloat16 kh = __float2bfloat16(kr);
    __nv_bfloat16 vh = __float2bfloat16(v);
    Qhi[idx] = qh; Qlo[idx] = __float2bfloat16(qr - __bfloat162float(qh));
    Khi[idx] = kh; Klo[idx] = __float2bfloat16(kr - __bfloat162float(kh));
    Vhi[idx] = vh; Vlo[idx] = __float2bfloat16(v  - __bfloat162float(vh));
}

// ---------------- tensor-core flash attention ----------------
// CTA: 128 q-rows x full head; 8 warps x 16 rows; k-tiles of 64, double-buffered.
#define ATQ 128
#define ATK 64
#define AROWB 272                      // 128 bf16 (256B) + 16B pad
#define Q_ARR (ATQ * AROWB)            // 34816
#define KV_ARR (ATK * AROWB)           // 17408
#define KV_STAGE (4 * KV_ARR)          // 69632 (Khi,Klo,Vhi,Vlo)
#define KV_OFF (2 * Q_ARR)             // 69632
#define ATTN_SMEM (KV_OFF + 2 * KV_STAGE)  // 208896
#define NKT (SEQ / ATK)                // 32

__global__ __launch_bounds__(256) void attn_mma_kernel(
    const __nv_bfloat16* __restrict__ Qhi, const __nv_bfloat16* __restrict__ Qlo,
    const __nv_bfloat16* __restrict__ Khi, const __nv_bfloat16* __restrict__ Klo,
    const __nv_bfloat16* __restrict__ Vhi, const __nv_bfloat16* __restrict__ Vlo,
    float* __restrict__ O)
{
    extern __shared__ __align__(128) char smraw[];
    const uint32_t smb = smem_u32(smraw);
    const int tid  = threadIdx.x;
    const int lane = tid & 31;
    const int wid  = tid >> 5;
    const int qBase = blockIdx.x * ATQ;
    const int h = blockIdx.y;
    const int b = blockIdx.z;
    const size_t bh = (size_t)b * NHEADS + h;

    const char* Qhg = (const char*)Qhi + (bh * SEQ + qBase) * (HD * 2);
    const char* Qlg = (const char*)Qlo + (bh * SEQ + qBase) * (HD * 2);
    const char* Khg = (const char*)Khi + bh * SEQ * (HD * 2);
    const char* Klg = (const char*)Klo + bh * SEQ * (HD * 2);
    const char* Vhg = (const char*)Vhi + bh * SEQ * (HD * 2);
    const char* Vlg = (const char*)Vlo + bh * SEQ * (HD * 2);

    // ---- load Q hi/lo (persistent smem) ----
    #pragma unroll
    for (int i = 0; i < 16; i++) {
        int idx = tid + i * 256;             // 4096 chunks
        int arr = idx >> 11;                 // 0:hi 1:lo
        int r   = (idx >> 4) & 127;
        int c   = (idx & 15) * 16;
        const char* sp = arr ? Qlg : Qhg;
        cp16(smb + arr * Q_ARR + r * AROWB + c, sp + (size_t)r * 256 + c);
    }
    asm volatile("cp.async.commit_group;" ::: "memory");

    auto loadKV = [&](int kt) {
        int s = kt & 1;
        #pragma unroll
        for (int i = 0; i < 16; i++) {
            int idx = tid + i * 256;         // 4096 chunks
            int arr = idx >> 10;             // 0..3
            int r   = (idx >> 4) & 63;
            int c   = (idx & 15) * 16;
            const char* sp = (arr == 0) ? Khg : (arr == 1) ? Klg
                           : (arr == 2) ? Vhg : Vlg;
            cp16(smb + KV_OFF + s * KV_STAGE + arr * KV_ARR + r * AROWB + c,
                 sp + (size_t)(kt * ATK + r) * 256 + c);
        }
        asm volatile("cp.async.commit_group;" ::: "memory");
    };

    loadKV(0);

    // ---- per-thread state ----
    float oAcc[16][4];
    #pragma unroll
    for (int t2 = 0; t2 < 16; t2++)
        #pragma unroll
        for (int u = 0; u < 4; u++) oAcc[t2][u] = 0.f;
    float mA = -INFINITY, mB = -INFINITY, lA = 0.f, lB = 0.f;

    const int m0 = wid * 16;
    const int a_row  = lane & 15;
    const int a_halfB = (lane >> 4) * 16;              // bytes
    const int b_row  = ((lane >> 4) << 3) + (lane & 7);
    const int b_halfB = ((lane >> 3) & 1) * 16;        // bytes
    const float SCALE = 0.08838834764831845f;          // 1/sqrt(128)

    for (int kt = 0; kt < NKT; kt++) {
        if (kt + 1 < NKT) {
            loadKV(kt + 1);
            asm volatile("cp.async.wait_group 1;" ::: "memory");
        } else {
            asm volatile("cp.async.wait_group 0;" ::: "memory");
        }
        __syncthreads();

        const uint32_t kb   = smb + KV_OFF + (kt & 1) * KV_STAGE;
        const uint32_t KhiS = kb;
        const uint32_t KloS = kb + KV_ARR;
        const uint32_t VhiS = kb + 2 * KV_ARR;
        const uint32_t VloS = kb + 3 * KV_ARR;

        // ---- S = scale * (Qhi Khi^T + Qlo Khi^T + Qhi Klo^T) ----
        float sAcc[8][4];
        #pragma unroll
        for (int ni = 0; ni < 8; ni++)
            #pragma unroll
            for (int u = 0; u < 4; u++) sAcc[ni][u] = 0.f;

        #pragma unroll
        for (int j = 0; j < 8; j++) {
            uint32_t ah[4], al[4];
            uint32_t aoff = (m0 + a_row) * AROWB + j * 32 + a_halfB;
            ldsm_x4(ah, smb + aoff);              // Qhi
            ldsm_x4(al, smb + Q_ARR + aoff);      // Qlo
            uint32_t bh_[4][4], bl_[4][4];
            #pragma unroll
            for (int nb = 0; nb < 4; nb++) {
                uint32_t boff = (nb * 16 + b_row) * AROWB + j * 32 + b_halfB;
                ldsm_x4(bh_[nb], KhiS + boff);
                ldsm_x4(bl_[nb], KloS + boff);
            }
            #pragma unroll
            for (int ni = 0; ni < 8; ni++) {
                const uint32_t* Bh = &bh_[ni >> 1][(ni & 1) * 2];
                const uint32_t* Bl = &bl_[ni >> 1][(ni & 1) * 2];
                mma_bf16(sAcc[ni], ah, Bh);
                mma_bf16(sAcc[ni], al, Bh);
                mma_bf16(sAcc[ni], ah, Bl);
            }
        }

        // ---- online softmax (rows r=lane>>2 and r+8, quad-local) ----
        float mxA = -INFINITY, mxB = -INFINITY;
        #pragma unroll
        for (int ni = 0; ni < 8; ni++) {
            #pragma unroll
            for (int u = 0; u < 4; u++) sAcc[ni][u] *= SCALE;
            mxA = fmaxf(mxA, fmaxf(sAcc[ni][0], sAcc[ni][1]));
            mxB = fmaxf(mxB, fmaxf(sAcc[ni][2], sAcc[ni][3]));
        }
        mxA = fmaxf(mxA, __shfl_xor_sync(0xffffffff, mxA, 1));
        mxA = fmaxf(mxA, __shfl_xor_sync(0xffffffff, mxA, 2));
        mxB = fmaxf(mxB, __shfl_xor_sync(0xffffffff, mxB, 1));
        mxB = fmaxf(mxB, __shfl_xor_sync(0xffffffff, mxB, 2));

        float mAn = fmaxf(mA, mxA), mBn = fmaxf(mB, mxB);
        float cA = __expf(mA - mAn), cB = __expf(mB - mBn);
        mA = mAn; mB = mBn;

        float sumA = 0.f, sumB = 0.f;
        #pragma unroll
        for (int ni = 0; ni < 8; ni++) {
            sAcc[ni][0] = __expf(sAcc[ni][0] - mA);
            sAcc[ni][1] = __expf(sAcc[ni][1] - mA);
            sAcc[ni][2] = __expf(sAcc[ni][2] - mB);
            sAcc[ni][3] = __expf(sAcc[ni][3] - mB);
            sumA += sAcc[ni][0] + sAcc[ni][1];
            sumB += sAcc[ni][2] + sAcc[ni][3];
        }
        sumA += __shfl_xor_sync(0xffffffff, sumA, 1);
        sumA += __shfl_xor_sync(0xffffffff, sumA, 2);
        sumB += __shfl_xor_sync(0xffffffff, sumB, 1);
        sumB += __shfl_xor_sync(0xffffffff, sumB, 2);
        lA = lA * cA + sumA;
        lB = lB * cB + sumB;

        // rescale O accumulators
        #pragma unroll
        for (int t2 = 0; t2 < 16; t2++) {
            oAcc[t2][0] *= cA; oAcc[t2][1] *= cA;
            oAcc[t2][2] *= cB; oAcc[t2][3] *= cB;
        }

        // ---- pack P into A-fragments (register-only) ----
        uint32_t phi[4][4], plo[4][4];
        #pragma unroll
        for (int j2 = 0; j2 < 4; j2++) {
            pack_hilo(sAcc[2*j2][0],   sAcc[2*j2][1],   phi[j2][0], plo[j2][0]);
            pack_hilo(sAcc[2*j2][2],   sAcc[2*j2][3],   phi[j2][1], plo[j2][1]);
            pack_hilo(sAcc[2*j2+1][0], sAcc[2*j2+1][1], phi[j2][2], plo[j2][2]);
            pack_hilo(sAcc[2*j2+1][2], sAcc[2*j2+1][3], phi[j2][3], plo[j2][3]);
        }

        // ---- O += (Phi Vhi + Plo Vhi + Phi Vlo) ----
        #pragma unroll
        for (int j2 = 0; j2 < 4; j2++) {
            int key0 = j2 * 16;
            #pragma unroll
            for (int nb = 0; nb < 8; nb++) {
                uint32_t vh[4], vl[4];
                uint32_t voff = (key0 + (lane & 15)) * AROWB
                              + (nb * 16 + ((lane >> 4) << 3)) * 2;
                ldsm_x4_t(vh, VhiS + voff);
                ldsm_x4_t(vl, VloS + voff);
                mma_bf16(oAcc[2*nb],   phi[j2], vh);
                mma_bf16(oAcc[2*nb],   plo[j2], vh);
                mma_bf16(oAcc[2*nb],   phi[j2], vl);
                mma_bf16(oAcc[2*nb+1], phi[j2], vh + 2);
                mma_bf16(oAcc[2*nb+1], plo[j2], vh + 2);
                mma_bf16(oAcc[2*nb+1], phi[j2], vl + 2);
            }
        }
        __syncthreads();
    }

    // ---- epilogue: normalize, write to [B,S,D] (head-contiguous) ----
    float invA = 1.0f / lA, invB = 1.0f / lB;
    int rA = qBase + m0 + (lane >> 2);
    int rB = rA + 8;
    float* outA = O + ((size_t)(b * SEQ + rA)) * D_MODEL + h * HD;
    float* outB = O + ((size_t)(b * SEQ + rB)) * D_MODEL + h * HD;
    #pragma unroll
    for (int t2 = 0; t2 < 16; t2++) {
        int cn = t2 * 8 + (lane & 3) * 2;
        float2 oa, ob;
        oa.x = oAcc[t2][0] * invA; oa.y = oAcc[t2][1] * invA;
        ob.x = oAcc[t2][2] * invB; ob.y = oAcc[t2][3] * invB;
        *(float2*)(outA + cn) = oa;
        *(float2*)(outB + cn) = ob;
    }
}

// ---------------- launch ----------------
extern "C" void kernel_launch(void* const* d_in, const int* in_sizes, int n_in,
                              void* d_out, int out_size)
{
    const float* x  = (const float*)d_in[0];
    const float* Wq = (const float*)d_in[1];
    const float* bq = (const float*)d_in[2];
    const float* Wk = (const float*)d_in[3];
    const float* bk = (const float*)d_in[4];
    const float* Wv = (const float*)d_in[5];
    const float* bv = (const float*)d_in[6];
    const float* Wo = (const float*)d_in[7];
    const float* bo = (const float*)d_in[8];
    float* out = (float*)d_out;

    float* scratch = nullptr;
    cudaGetSymbolAddress((void**)&scratch, g_scratch);
    const size_t NMe = (size_t)MROWS * D_MODEL;
    float* Qlin = scratch + 0 * NMe;
    float* Klin = scratch + 1 * NMe;
    float* Vlin = scratch + 2 * NMe;
    float* AO   = scratch + 3 * NMe;

    __nv_bfloat16* bfp = nullptr;
    cudaGetSymbolAddress((void**)&bfp, g_bf16);
    const size_t XH = (size_t)MROWS * KTOT;
    const size_t WH = (size_t)D_MODEL * KTOT;
    __nv_bfloat16* Xhat  = bfp;
    __nv_bfloat16* AOhat = bfp + XH;
    __nv_bfloat16* WqH   = bfp + 2 * XH;
    __nv_bfloat16* WkH   = WqH + WH;
    __nv_bfloat16* WvH   = WkH + WH;
    __nv_bfloat16* WoH   = WvH + WH;

    __nv_bfloat16* ap = nullptr;
    cudaGetSymbolAddress((void**)&ap, g_attn);
    const size_t AH = (size_t)BHS * HD;
    __nv_bfloat16* Qhi = ap + 0 * AH;
    __nv_bfloat16* Qlo = ap + 1 * AH;
    __nv_bfloat16* Khi = ap + 2 * AH;
    __nv_bfloat16* Klo = ap + 3 * AH;
    __nv_bfloat16* Vhi = ap + 4 * AH;
    __nv_bfloat16* Vlo = ap + 5 * AH;

    cudaFuncSetAttribute(gemm_mma_kernel, cudaFuncAttributeMaxDynamicSharedMemorySize,
                         GEMM_SMEM);
    cudaFuncSetAttribute(attn_mma_kernel, cudaFuncAttributeMaxDynamicSharedMemorySize,
                         ATTN_SMEM);

    // split operands to 3-term bf16
    split_kernel<<<(MROWS * D_MODEL) / 256, 256>>>(x,  Xhat, 0);
    split_kernel<<<(D_MODEL * D_MODEL) / 256, 256>>>(Wq, WqH, 1);
    split_kernel<<<(D_MODEL * D_MODEL) / 256, 256>>>(Wk, WkH, 1);
    split_kernel<<<(D_MODEL * D_MODEL) / 256, 256>>>(Wv, WvH, 1);
    split_kernel<<<(D_MODEL * D_MODEL) / 256, 256>>>(Wo, WoH, 1);

    dim3 ggrid(D_MODEL / BN, MROWS / BM);   // (16, 32)
    gemm_mma_kernel<<<ggrid, 256, GEMM_SMEM>>>(Xhat, WqH, bq, Qlin, MROWS, D_MODEL);
    gemm_mma_kernel<<<ggrid, 256, GEMM_SMEM>>>(Xhat, WkH, bk, Klin, MROWS, D_MODEL);
    gemm_mma_kernel<<<ggrid, 256, GEMM_SMEM>>>(Xhat, WvH, bv, Vlin, MROWS, D_MODEL);

    int total = BATCH * NHEADS * SEQ * HD;
    rope_split_kernel<<<total / 256, 256>>>(Qlin, Klin, Vlin,
                                            Qhi, Qlo, Khi, Klo, Vhi, Vlo);

    attn_mma_kernel<<<dim3(SEQ / ATQ, NHEADS, BATCH), 256, ATTN_SMEM>>>(
        Qhi, Qlo, Khi, Klo, Vhi, Vlo, AO);

    split_kernel<<<(MROWS * D_MODEL) / 256, 256>>>(AO, AOhat, 0);
    gemm_mma_kernel<<<ggrid, 256, GEMM_SMEM>>>(AOhat, WoH, bo, out, MROWS, D_MODEL);
}